// round 4
// baseline (speedup 1.0000x reference)
#include <cuda_runtime.h>
#include <math_constants.h>

#define Bn 128
#define Tn 512
#define Kn 256
#define HB 64   // half of Bn: CTAs in k1, each owning batches (b, b+HB)

// ---------------- scratch (static device globals; no allocation allowed) ----
__device__ float2        g_ET[Kn * Kn];                 // (exp(trans), trans) interleaved
__device__ unsigned char g_bp[(size_t)Bn * Tn * Kn];    // Viterbi backpointers (16.7 MB)
__device__ float         g_logZ[Bn];
__device__ float         g_score[Bn];
__device__ int           g_best[Bn];
__device__ int           g_pred[Bn * Tn];

// ---------------- K0: build interleaved (exp(t), t) matrix --------------------
__global__ void k0_prep(const float* __restrict__ trans) {
    int idx = blockIdx.x * blockDim.x + threadIdx.x;
    if (idx < Kn * Kn) {
        float t = trans[idx];
        g_ET[idx] = make_float2(__expf(t), t);
    }
}

// ---------------- K1: fused forward(logZ) + Viterbi scan, 2 batches/CTA -------
// CTA x owns batches b0=x and b1=x+HB. Thread j owns output state j for both.
// Each ET element loaded once per step serves both batches -> L2 traffic halved.
__global__ __launch_bounds__(Kn) void k1_scan2(
    const float* __restrict__ logit,
    const float* __restrict__ startv,
    const float* __restrict__ endv,
    const int*   __restrict__ seq_lens)
{
    int b0 = blockIdx.x;
    int b1 = blockIdx.x + HB;
    int j = threadIdx.x;
    int lane = j & 31, w = j >> 5;

    __shared__ float2 pva0[Kn];   // (p_i, viterbi alpha_i) batch 0
    __shared__ float2 pva1[Kn];   // batch 1
    __shared__ float  red0[8], red1[8];

    int L0 = seq_lens[b0];
    int L1 = seq_lens[b1];
    int Lmax = max(L0, L1);

    const float* em0 = logit + (size_t)b0 * Tn * Kn;
    const float* em1 = logit + (size_t)b1 * Tn * Kn;
    unsigned char* bpb0 = g_bp + (size_t)b0 * Tn * Kn;
    unsigned char* bpb1 = g_bp + (size_t)b1 * Tn * Kn;

    float sv = startv[j];
    float af0 = sv + em0[j], av0 = af0;
    float af1 = sv + em1[j], av1 = af1;

    for (int t = 1; t < Lmax; ++t) {
        bool act0 = t < L0, act1 = t < L1;
        // hoisted emission loads (always in-bounds: t < Tn)
        float e0 = __ldg(em0 + t * Kn + j);
        float e1 = __ldg(em1 + t * Kn + j);

        // ---- fused block max over both forward alphas ----
        float m0 = af0, m1 = af1;
        #pragma unroll
        for (int o = 16; o; o >>= 1) {
            m0 = fmaxf(m0, __shfl_xor_sync(0xffffffffu, m0, o));
            m1 = fmaxf(m1, __shfl_xor_sync(0xffffffffu, m1, o));
        }
        if (lane == 0) { red0[w] = m0; red1[w] = m1; }
        __syncthreads();
        m0 = fmaxf(fmaxf(fmaxf(red0[0], red0[1]), fmaxf(red0[2], red0[3])),
                   fmaxf(fmaxf(red0[4], red0[5]), fmaxf(red0[6], red0[7])));
        m1 = fmaxf(fmaxf(fmaxf(red1[0], red1[1]), fmaxf(red1[2], red1[3])),
                   fmaxf(fmaxf(red1[4], red1[5]), fmaxf(red1[6], red1[7])));

        pva0[j] = make_float2(__expf(af0 - m0), av0);
        pva1[j] = make_float2(__expf(af1 - m1), av1);
        __syncthreads();

        // ---- inner K-loop: one ET load feeds both batches ----
        float s0 = 0.f, s1 = 0.f;
        float bv0 = -CUDART_INF_F, bv1 = -CUDART_INF_F;
        int   bi0 = 0, bi1 = 0;
        const float2* ET = g_ET + j;
        #pragma unroll 8
        for (int i = 0; i < Kn; ++i) {
            float2 et = ET[i * Kn];       // (E_ij, trans_ij), coalesced per warp
            float2 p0 = pva0[i];          // shared broadcast
            float2 p1 = pva1[i];
            s0 += p0.x * et.x;
            s1 += p1.x * et.x;
            float v0 = p0.y + et.y;       // exact fp32 add, same as reference
            float v1 = p1.y + et.y;
            if (v0 > bv0) { bv0 = v0; bi0 = i; }   // strict > : first argmax
            if (v1 > bv1) { bv1 = v1; bi1 = i; }
        }

        if (act0) {
            af0 = m0 + __logf(s0) + e0;
            av0 = bv0 + e0;
            bpb0[t * Kn + j] = (unsigned char)bi0;
        }
        if (act1) {
            af1 = m1 + __logf(s1) + e1;
            av1 = bv1 + e1;
            bpb1[t * Kn + j] = (unsigned char)bi1;
        }
        __syncthreads();
    }

    // ---- epilogue for both batches: logZ + best_last ----
    float ev = endv[j];
    float afs[2] = { af0, af1 };
    float avs[2] = { av0, av1 };
    int   bs[2]  = { b0, b1 };

    #pragma unroll
    for (int sH = 0; sH < 2; ++sH) {
        float z = afs[sH] + ev;
        float m2 = z;
        #pragma unroll
        for (int o = 16; o; o >>= 1) m2 = fmaxf(m2, __shfl_xor_sync(0xffffffffu, m2, o));
        if (lane == 0) red0[w] = m2;
        __syncthreads();
        m2 = fmaxf(fmaxf(fmaxf(red0[0], red0[1]), fmaxf(red0[2], red0[3])),
                   fmaxf(fmaxf(red0[4], red0[5]), fmaxf(red0[6], red0[7])));
        float ex = __expf(z - m2);
        #pragma unroll
        for (int o = 16; o; o >>= 1) ex += __shfl_xor_sync(0xffffffffu, ex, o);
        __syncthreads();
        if (lane == 0) red0[w] = ex;
        __syncthreads();
        if (j == 0) {
            float ssum = red0[0] + red0[1] + red0[2] + red0[3]
                       + red0[4] + red0[5] + red0[6] + red0[7];
            g_logZ[bs[sH]] = m2 + __logf(ssum);
        }

        // best_last: first argmax(viterbi alpha + end), exact linear scan
        pva0[j].x = avs[sH] + ev;
        __syncthreads();
        if (j == 0) {
            float bv = pva0[0].x; int bi = 0;
            for (int i = 1; i < Kn; ++i) {
                float v = pva0[i].x;
                if (v > bv) { bv = v; bi = i; }
            }
            g_best[bs[sH]] = bi;
        }
        __syncthreads();
    }
}

// ---------------- K2: gold-path score per batch ------------------------------
__global__ void k2_score(
    const float* __restrict__ logit,
    const float* __restrict__ trans,
    const float* __restrict__ startv,
    const float* __restrict__ endv,
    const int*   __restrict__ target,
    const int*   __restrict__ seq_lens)
{
    int b = blockIdx.x, tid = threadIdx.x;
    int L = seq_lens[b];
    const int*   tg = target + b * Tn;
    const float* em = logit + (size_t)b * Tn * Kn;

    float part = 0.f;
    for (int t = 1 + tid; t < L; t += blockDim.x) {
        int cur = tg[t], prev = tg[t - 1];
        part += trans[prev * Kn + cur] + em[t * Kn + cur];
    }
    #pragma unroll
    for (int o = 16; o; o >>= 1) part += __shfl_xor_sync(0xffffffffu, part, o);
    __shared__ float red[4];
    if ((tid & 31) == 0) red[tid >> 5] = part;
    __syncthreads();
    if (tid == 0) {
        float s = red[0] + red[1] + red[2] + red[3];
        int t0 = tg[0];
        s += startv[t0] + em[t0];
        s += endv[tg[L - 1]];
        g_score[b] = s;
    }
}

// ---------------- K3: loss = mean(logZ - score) ------------------------------
__global__ void k3_loss(float* __restrict__ out) {
    int b = threadIdx.x;  // 128 threads
    float v = g_logZ[b] - g_score[b];
    #pragma unroll
    for (int o = 16; o; o >>= 1) v += __shfl_xor_sync(0xffffffffu, v, o);
    __shared__ float red[4];
    if ((b & 31) == 0) red[b >> 5] = v;
    __syncthreads();
    if (b == 0) out[0] = (red[0] + red[1] + red[2] + red[3]) / (float)Bn;
}

// ---------------- K4: Viterbi backtrace (128 independent chains) -------------
__global__ void k4_backtrace(const int* __restrict__ seq_lens,
                             float* __restrict__ out_pred)
{
    int b = threadIdx.x;
    if (b >= Bn) return;
    int L = seq_lens[b];
    int tag = g_best[b];
    g_pred[b * Tn + Tn - 1] = tag;
    out_pred[b * Tn + Tn - 1] = (float)tag;
    const unsigned char* bpb = g_bp + (size_t)b * Tn * Kn;
    for (int s = Tn - 2; s >= 0; --s) {
        int t = s + 1;
        if (t < L) tag = bpb[t * Kn + tag];   // masked step: identity (bp == idK)
        g_pred[b * Tn + s] = tag;
        out_pred[b * Tn + s] = (float)tag;
    }
}

// ---------------- K5: rearrange + log_softmax --------------------------------
__global__ __launch_bounds__(Kn) void k5_logits(
    const float* __restrict__ logit,
    float* __restrict__ out_lp)
{
    int row = blockIdx.x;   // b*T + t
    int j = threadIdx.x;
    int lane = j & 31, w = j >> 5;

    const float* x = logit + (size_t)row * Kn;
    float xv = x[j];

    __shared__ float sh[Kn];
    __shared__ float redv[8];
    __shared__ int   redi[8];
    sh[j] = xv;

    // argmax with first-index tie-break (exact jnp.argmax semantics)
    float bv = xv; int bi = j;
    #pragma unroll
    for (int o = 16; o; o >>= 1) {
        float ov = __shfl_xor_sync(0xffffffffu, bv, o);
        int   oi = __shfl_xor_sync(0xffffffffu, bi, o);
        if (ov > bv || (ov == bv && oi < bi)) { bv = ov; bi = oi; }
    }
    if (lane == 0) { redv[w] = bv; redi[w] = bi; }
    __syncthreads();
    float mv = redv[0]; int mi = redi[0];
    #pragma unroll
    for (int k = 1; k < 8; ++k) {
        float ov = redv[k]; int oi = redi[k];
        if (ov > mv || (ov == mv && oi < mi)) { mv = ov; mi = oi; }
    }

    int p = g_pred[row];
    float labv = sh[p];

    float y = xv;
    if (j == p)  y = mv;     // out.at[pred].set(maxv)
    if (j == mi) y = labv;   // out.at[argm].set(labv)  (applied second, as in ref)

    // log_softmax: max of rearranged array == mv (value multiset preserved)
    float ex = __expf(y - mv);
    #pragma unroll
    for (int o = 16; o; o >>= 1) ex += __shfl_xor_sync(0xffffffffu, ex, o);
    __syncthreads();
    if (lane == 0) redv[w] = ex;
    __syncthreads();
    float ssum = redv[0] + redv[1] + redv[2] + redv[3]
               + redv[4] + redv[5] + redv[6] + redv[7];
    out_lp[(size_t)row * Kn + j] = y - mv - __logf(ssum);
}

// ---------------- launch ------------------------------------------------------
extern "C" void kernel_launch(void* const* d_in, const int* in_sizes, int n_in,
                              void* d_out, int out_size)
{
    (void)in_sizes; (void)n_in; (void)out_size;
    const float* logit  = (const float*)d_in[0];   // [B,T,K] f32
    const float* trans  = (const float*)d_in[1];   // [K,K]   f32
    const float* startv = (const float*)d_in[2];   // [K]     f32
    const float* endv   = (const float*)d_in[3];   // [K]     f32
    const int*   target = (const int*)d_in[4];     // [B,T]   i32
    const int*   seqlen = (const int*)d_in[5];     // [B]     i32

    float* out      = (float*)d_out;
    float* out_pred = out + 1;              // [B,T]   (pred cast to f32)
    float* out_lp   = out + 1 + Bn * Tn;    // [B,T,K]

    k0_prep<<<(Kn * Kn + 255) / 256, 256>>>(trans);
    k1_scan2<<<HB, Kn>>>(logit, startv, endv, seqlen);
    k2_score<<<Bn, 128>>>(logit, trans, startv, endv, target, seqlen);
    k3_loss<<<1, 128>>>(out);
    k4_backtrace<<<1, 128>>>(seqlen, out_pred);
    k5_logits<<<Bn * Tn, Kn>>>(logit, out_lp);
}

// round 6
// speedup vs baseline: 1.3591x; 1.3591x over previous
#include <cuda_runtime.h>
#include <math_constants.h>

#define Bn 128
#define Tn 512
#define Kn 256
#define HB 64   // half of Bn: CTAs in k1, each owning batches (b, b+HB)

// ---------------- scratch (static device globals; no allocation allowed) ----
// +16 pad: prefetch pipeline may issue one tile of loads past the end.
__device__ float2        g_ET[Kn * Kn + 16];            // (exp(trans), trans) interleaved
__device__ unsigned char g_bp[(size_t)Bn * Tn * Kn];    // Viterbi backpointers (16.7 MB)
__device__ float         g_logZ[Bn];
__device__ float         g_score[Bn];
__device__ int           g_best[Bn];
__device__ int           g_pred[Bn * Tn];

// ---------------- K0: build interleaved (exp(t), t) matrix --------------------
__global__ void k0_prep(const float* __restrict__ trans) {
    int idx = blockIdx.x * blockDim.x + threadIdx.x;
    if (idx < Kn * Kn) {
        float t = trans[idx];
        g_ET[idx] = make_float2(__expf(t), t);
    }
}

// ---------------- K1: fused forward(logZ) + Viterbi scan, 2 batches/CTA -------
// CTA x owns batches b0=x and b1=x+HB. Thread j owns output state j for both.
// ET stream is register-tiled (8-wide ping-pong prefetch, __ldcg) so the
// L2 loads run at MLP~8-16 instead of ~2; pva packed as float4 (1 LDS.128).
__global__ __launch_bounds__(Kn) void k1_scan2(
    const float* __restrict__ logit,
    const float* __restrict__ startv,
    const float* __restrict__ endv,
    const int*   __restrict__ seq_lens)
{
    int b0 = blockIdx.x;
    int b1 = blockIdx.x + HB;
    int j = threadIdx.x;
    int lane = j & 31, w = j >> 5;

    __shared__ float4 pva[Kn];    // (p0_i, av0_i, p1_i, av1_i)
    __shared__ float  red0[8], red1[8];

    int L0 = seq_lens[b0];
    int L1 = seq_lens[b1];
    int Lmax = max(L0, L1);

    const float* em0 = logit + (size_t)b0 * Tn * Kn;
    const float* em1 = logit + (size_t)b1 * Tn * Kn;
    unsigned char* bpb0 = g_bp + (size_t)b0 * Tn * Kn;
    unsigned char* bpb1 = g_bp + (size_t)b1 * Tn * Kn;

    float sv = startv[j];
    float af0 = sv + em0[j], av0 = af0;
    float af1 = sv + em1[j], av1 = af1;

    const float2* ETp = g_ET + j;   // column j; row stride Kn float2

    for (int t = 1; t < Lmax; ++t) {
        bool act0 = t < L0, act1 = t < L1;
        // hoisted emission loads (always in-bounds: t < Tn)
        float e0 = __ldg(em0 + t * Kn + j);
        float e1 = __ldg(em1 + t * Kn + j);

        // ---- fused block max over both forward alphas ----
        float m0 = af0, m1 = af1;
        #pragma unroll
        for (int o = 16; o; o >>= 1) {
            m0 = fmaxf(m0, __shfl_xor_sync(0xffffffffu, m0, o));
            m1 = fmaxf(m1, __shfl_xor_sync(0xffffffffu, m1, o));
        }
        if (lane == 0) { red0[w] = m0; red1[w] = m1; }
        __syncthreads();
        m0 = fmaxf(fmaxf(fmaxf(red0[0], red0[1]), fmaxf(red0[2], red0[3])),
                   fmaxf(fmaxf(red0[4], red0[5]), fmaxf(red0[6], red0[7])));
        m1 = fmaxf(fmaxf(fmaxf(red1[0], red1[1]), fmaxf(red1[2], red1[3])),
                   fmaxf(fmaxf(red1[4], red1[5]), fmaxf(red1[6], red1[7])));

        pva[j] = make_float4(__expf(af0 - m0), av0, __expf(af1 - m1), av1);
        __syncthreads();

        // ---- inner K-loop: software-pipelined register tiles of 8 ----
        float s0 = 0.f, s1 = 0.f;
        float bv0 = -CUDART_INF_F, bv1 = -CUDART_INF_F;
        int   bi0 = 0, bi1 = 0;

        float2 ea[8], eb[8];
        #pragma unroll
        for (int u = 0; u < 8; ++u) ea[u] = __ldcg(ETp + u * Kn);

        const float4* pv_ptr = pva;

        #pragma unroll 1
        for (int i0 = 0; i0 < Kn; i0 += 16) {
            // prefetch next half-tile [i0+8 .. i0+15]
            #pragma unroll
            for (int u = 0; u < 8; ++u) eb[u] = __ldcg(ETp + (i0 + 8 + u) * Kn);
            // compute on ea = [i0 .. i0+7]
            #pragma unroll
            for (int u = 0; u < 8; ++u) {
                float4 pv = pv_ptr[u];
                float2 et = ea[u];
                s0 += pv.x * et.x;
                s1 += pv.z * et.x;
                float v0 = pv.y + et.y;       // exact fp32 add, same as reference
                float v1 = pv.w + et.y;
                if (v0 > bv0) { bv0 = v0; bi0 = i0 + u; }   // strict >: first argmax
                if (v1 > bv1) { bv1 = v1; bi1 = i0 + u; }
            }
            // prefetch following half-tile [i0+16 .. i0+23] (last one reads pad)
            #pragma unroll
            for (int u = 0; u < 8; ++u) ea[u] = __ldcg(ETp + (i0 + 16 + u) * Kn);
            // compute on eb = [i0+8 .. i0+15]
            #pragma unroll
            for (int u = 0; u < 8; ++u) {
                float4 pv = pv_ptr[8 + u];
                float2 et = eb[u];
                s0 += pv.x * et.x;
                s1 += pv.z * et.x;
                float v0 = pv.y + et.y;
                float v1 = pv.w + et.y;
                if (v0 > bv0) { bv0 = v0; bi0 = i0 + 8 + u; }
                if (v1 > bv1) { bv1 = v1; bi1 = i0 + 8 + u; }
            }
            pv_ptr += 16;
        }

        if (act0) {
            af0 = m0 + __logf(s0) + e0;
            av0 = bv0 + e0;
            bpb0[t * Kn + j] = (unsigned char)bi0;
        }
        if (act1) {
            af1 = m1 + __logf(s1) + e1;
            av1 = bv1 + e1;
            bpb1[t * Kn + j] = (unsigned char)bi1;
        }
        __syncthreads();
    }

    // ---- epilogue for both batches: logZ + best_last ----
    float ev = endv[j];
    float afs[2] = { af0, af1 };
    float avs[2] = { av0, av1 };
    int   bs[2]  = { b0, b1 };

    #pragma unroll
    for (int sH = 0; sH < 2; ++sH) {
        float z = afs[sH] + ev;
        float m2 = z;
        #pragma unroll
        for (int o = 16; o; o >>= 1) m2 = fmaxf(m2, __shfl_xor_sync(0xffffffffu, m2, o));
        if (lane == 0) red0[w] = m2;
        __syncthreads();
        m2 = fmaxf(fmaxf(fmaxf(red0[0], red0[1]), fmaxf(red0[2], red0[3])),
                   fmaxf(fmaxf(red0[4], red0[5]), fmaxf(red0[6], red0[7])));
        float ex = __expf(z - m2);
        #pragma unroll
        for (int o = 16; o; o >>= 1) ex += __shfl_xor_sync(0xffffffffu, ex, o);
        __syncthreads();
        if (lane == 0) red0[w] = ex;
        __syncthreads();
        if (j == 0) {
            float ssum = red0[0] + red0[1] + red0[2] + red0[3]
                       + red0[4] + red0[5] + red0[6] + red0[7];
            g_logZ[bs[sH]] = m2 + __logf(ssum);
        }

        // best_last: first argmax(viterbi alpha + end), exact linear scan
        pva[j].x = avs[sH] + ev;
        __syncthreads();
        if (j == 0) {
            float bv = pva[0].x; int bi = 0;
            for (int i = 1; i < Kn; ++i) {
                float v = pva[i].x;
                if (v > bv) { bv = v; bi = i; }
            }
            g_best[bs[sH]] = bi;
        }
        __syncthreads();
    }
}

// ---------------- K2: gold-path score per batch ------------------------------
__global__ void k2_score(
    const float* __restrict__ logit,
    const float* __restrict__ trans,
    const float* __restrict__ startv,
    const float* __restrict__ endv,
    const int*   __restrict__ target,
    const int*   __restrict__ seq_lens)
{
    int b = blockIdx.x, tid = threadIdx.x;
    int L = seq_lens[b];
    const int*   tg = target + b * Tn;
    const float* em = logit + (size_t)b * Tn * Kn;

    float part = 0.f;
    for (int t = 1 + tid; t < L; t += blockDim.x) {
        int cur = tg[t], prev = tg[t - 1];
        part += trans[prev * Kn + cur] + em[t * Kn + cur];
    }
    #pragma unroll
    for (int o = 16; o; o >>= 1) part += __shfl_xor_sync(0xffffffffu, part, o);
    __shared__ float red[4];
    if ((tid & 31) == 0) red[tid >> 5] = part;
    __syncthreads();
    if (tid == 0) {
        float s = red[0] + red[1] + red[2] + red[3];
        int t0 = tg[0];
        s += startv[t0] + em[t0];
        s += endv[tg[L - 1]];
        g_score[b] = s;
    }
}

// ---------------- K3: loss = mean(logZ - score) ------------------------------
__global__ void k3_loss(float* __restrict__ out) {
    int b = threadIdx.x;  // 128 threads
    float v = g_logZ[b] - g_score[b];
    #pragma unroll
    for (int o = 16; o; o >>= 1) v += __shfl_xor_sync(0xffffffffu, v, o);
    __shared__ float red[4];
    if ((b & 31) == 0) red[b >> 5] = v;
    __syncthreads();
    if (b == 0) out[0] = (red[0] + red[1] + red[2] + red[3]) / (float)Bn;
}

// ---------------- K4: Viterbi backtrace (128 independent chains) -------------
__global__ void k4_backtrace(const int* __restrict__ seq_lens,
                             float* __restrict__ out_pred)
{
    int b = threadIdx.x;
    if (b >= Bn) return;
    int L = seq_lens[b];
    int tag = g_best[b];
    g_pred[b * Tn + Tn - 1] = tag;
    out_pred[b * Tn + Tn - 1] = (float)tag;
    const unsigned char* bpb = g_bp + (size_t)b * Tn * Kn;
    for (int s = Tn - 2; s >= 0; --s) {
        int t = s + 1;
        if (t < L) tag = bpb[t * Kn + tag];   // masked step: identity (bp == idK)
        g_pred[b * Tn + s] = tag;
        out_pred[b * Tn + s] = (float)tag;
    }
}

// ---------------- K5: rearrange + log_softmax --------------------------------
__global__ __launch_bounds__(Kn) void k5_logits(
    const float* __restrict__ logit,
    float* __restrict__ out_lp)
{
    int row = blockIdx.x;   // b*T + t
    int j = threadIdx.x;
    int lane = j & 31, w = j >> 5;

    const float* x = logit + (size_t)row * Kn;
    float xv = x[j];

    __shared__ float sh[Kn];
    __shared__ float redv[8];
    __shared__ int   redi[8];
    sh[j] = xv;

    // argmax with first-index tie-break (exact jnp.argmax semantics)
    float bv = xv; int bi = j;
    #pragma unroll
    for (int o = 16; o; o >>= 1) {
        float ov = __shfl_xor_sync(0xffffffffu, bv, o);
        int   oi = __shfl_xor_sync(0xffffffffu, bi, o);
        if (ov > bv || (ov == bv && oi < bi)) { bv = ov; bi = oi; }
    }
    if (lane == 0) { redv[w] = bv; redi[w] = bi; }
    __syncthreads();
    float mv = redv[0]; int mi = redi[0];
    #pragma unroll
    for (int k = 1; k < 8; ++k) {
        float ov = redv[k]; int oi = redi[k];
        if (ov > mv || (ov == mv && oi < mi)) { mv = ov; mi = oi; }
    }

    int p = g_pred[row];
    float labv = sh[p];

    float y = xv;
    if (j == p)  y = mv;     // out.at[pred].set(maxv)
    if (j == mi) y = labv;   // out.at[argm].set(labv)  (applied second, as in ref)

    // log_softmax: max of rearranged array == mv (value multiset preserved)
    float ex = __expf(y - mv);
    #pragma unroll
    for (int o = 16; o; o >>= 1) ex += __shfl_xor_sync(0xffffffffu, ex, o);
    __syncthreads();
    if (lane == 0) redv[w] = ex;
    __syncthreads();
    float ssum = redv[0] + redv[1] + redv[2] + redv[3]
               + redv[4] + redv[5] + redv[6] + redv[7];
    out_lp[(size_t)row * Kn + j] = y - mv - __logf(ssum);
}

// ---------------- launch ------------------------------------------------------
extern "C" void kernel_launch(void* const* d_in, const int* in_sizes, int n_in,
                              void* d_out, int out_size)
{
    (void)in_sizes; (void)n_in; (void)out_size;
    const float* logit  = (const float*)d_in[0];   // [B,T,K] f32
    const float* trans  = (const float*)d_in[1];   // [K,K]   f32
    const float* startv = (const float*)d_in[2];   // [K]     f32
    const float* endv   = (const float*)d_in[3];   // [K]     f32
    const int*   target = (const int*)d_in[4];     // [B,T]   i32
    const int*   seqlen = (const int*)d_in[5];     // [B]     i32

    float* out      = (float*)d_out;
    float* out_pred = out + 1;              // [B,T]   (pred cast to f32)
    float* out_lp   = out + 1 + Bn * Tn;    // [B,T,K]

    k0_prep<<<(Kn * Kn + 255) / 256, 256>>>(trans);
    k1_scan2<<<HB, Kn>>>(logit, startv, endv, seqlen);
    k2_score<<<Bn, 128>>>(logit, trans, startv, endv, target, seqlen);
    k3_loss<<<1, 128>>>(out);
    k4_backtrace<<<1, 128>>>(seqlen, out_pred);
    k5_logits<<<Bn * Tn, Kn>>>(logit, out_lp);
}

// round 7
// speedup vs baseline: 1.6749x; 1.2323x over previous
#include <cuda_runtime.h>
#include <math_constants.h>

#define Bn 128
#define Tn 512
#define Kn 256
#define HB 64   // half of Bn: CTAs in k1, each owning batches (b, b+HB)

// ---------------- scratch (static device globals; no allocation allowed) ----
// pad: prefetch pipeline reads up to 8 rows past row 255 -> 8*Kn extra.
__device__ float2        g_ET[Kn * Kn + 8 * Kn];        // (exp(trans), trans) interleaved
__device__ unsigned char g_bp[(size_t)Bn * Tn * Kn];    // Viterbi backpointers (16.7 MB)
__device__ float         g_logZ[Bn];
__device__ float         g_score[Bn];
__device__ int           g_best[Bn];
__device__ int           g_pred[Bn * Tn];

// ---------------- K0: build interleaved (exp(t), t) matrix --------------------
__global__ void k0_prep(const float* __restrict__ trans) {
    int idx = blockIdx.x * blockDim.x + threadIdx.x;
    if (idx < Kn * Kn) {
        float t = trans[idx];
        g_ET[idx] = make_float2(__expf(t), t);
    }
}

// ---------------- K1: fused forward(logZ) + Viterbi scan ----------------------
// 2 batches/CTA, 512 threads: thread (j, h) owns output state j (=tid&255) and
// source half h (=tid>>8, i in [h*128, h*128+128)). 4 warps/SMSP overlap the
// ET prefetch stalls. h=1 writes partials to SMEM; h=0 combines (first-index
// argmax across halves preserved exactly) and owns alpha/bp updates.
__global__ __launch_bounds__(512) void k1_scan2(
    const float* __restrict__ logit,
    const float* __restrict__ startv,
    const float* __restrict__ endv,
    const int*   __restrict__ seq_lens)
{
    int b0 = blockIdx.x;
    int b1 = blockIdx.x + HB;
    int tid = threadIdx.x;
    int j = tid & 255;
    int h = tid >> 8;
    int lane = tid & 31, w = tid >> 5;   // w in 0..15; h0 warps are 0..7

    __shared__ float4 pva[Kn];     // (p0_i, av0_i, p1_i, av1_i)
    __shared__ float4 partS[Kn];   // h=1 partials: (s0, s1, bv0, bv1)
    __shared__ int2   partI[Kn];   // h=1 partials: (bi0, bi1)
    __shared__ float  red0[8], red1[8];

    int L0 = seq_lens[b0];
    int L1 = seq_lens[b1];
    int Lmax = max(L0, L1);

    const float* em0 = logit + (size_t)b0 * Tn * Kn;
    const float* em1 = logit + (size_t)b1 * Tn * Kn;
    unsigned char* bpb0 = g_bp + (size_t)b0 * Tn * Kn;
    unsigned char* bpb1 = g_bp + (size_t)b1 * Tn * Kn;

    float af0 = 0.f, av0 = 0.f, af1 = 0.f, av1 = 0.f;
    if (h == 0) {
        float sv = startv[j];
        af0 = sv + em0[j]; av0 = af0;
        af1 = sv + em1[j]; av1 = af1;
    }

    int hbase = h << 7;                               // 0 or 128
    const float2* ETp = g_ET + j + (size_t)hbase * Kn;

    for (int t = 1; t < Lmax; ++t) {
        bool act0 = t < L0, act1 = t < L1;

        float e0 = 0.f, e1 = 0.f, m0 = 0.f, m1 = 0.f;
        if (h == 0) {
            // hoisted emission loads (always in-bounds: t < Tn)
            e0 = __ldg(em0 + t * Kn + j);
            e1 = __ldg(em1 + t * Kn + j);
            // warp part of block max over forward alphas (warps 0..7 only)
            m0 = af0; m1 = af1;
            #pragma unroll
            for (int o = 16; o; o >>= 1) {
                m0 = fmaxf(m0, __shfl_xor_sync(0xffffffffu, m0, o));
                m1 = fmaxf(m1, __shfl_xor_sync(0xffffffffu, m1, o));
            }
            if (lane == 0) { red0[w] = m0; red1[w] = m1; }
        }
        __syncthreads();
        if (h == 0) {
            m0 = fmaxf(fmaxf(fmaxf(red0[0], red0[1]), fmaxf(red0[2], red0[3])),
                       fmaxf(fmaxf(red0[4], red0[5]), fmaxf(red0[6], red0[7])));
            m1 = fmaxf(fmaxf(fmaxf(red1[0], red1[1]), fmaxf(red1[2], red1[3])),
                       fmaxf(fmaxf(red1[4], red1[5]), fmaxf(red1[6], red1[7])));
            pva[j] = make_float4(__expf(af0 - m0), av0, __expf(af1 - m1), av1);
        }
        __syncthreads();

        // ---- inner half-K loop: software-pipelined register tiles of 8 ----
        float s0 = 0.f, s1 = 0.f;
        float bv0 = -CUDART_INF_F, bv1 = -CUDART_INF_F;
        int   bi0 = hbase, bi1 = hbase;

        float2 ea[8], eb[8];
        #pragma unroll
        for (int u = 0; u < 8; ++u) ea[u] = __ldcg(ETp + u * Kn);

        const float4* pv_ptr = pva + hbase;

        #pragma unroll 1
        for (int i0 = 0; i0 < 128; i0 += 16) {
            // prefetch next half-tile
            #pragma unroll
            for (int u = 0; u < 8; ++u) eb[u] = __ldcg(ETp + (i0 + 8 + u) * Kn);
            #pragma unroll
            for (int u = 0; u < 8; ++u) {
                float4 pv = pv_ptr[u];
                float2 et = ea[u];
                s0 += pv.x * et.x;
                s1 += pv.z * et.x;
                float v0 = pv.y + et.y;       // exact fp32 add, same as reference
                float v1 = pv.w + et.y;
                if (v0 > bv0) { bv0 = v0; bi0 = hbase + i0 + u; }   // strict >
                if (v1 > bv1) { bv1 = v1; bi1 = hbase + i0 + u; }
            }
            // prefetch following half-tile (tail lands in the pad rows)
            #pragma unroll
            for (int u = 0; u < 8; ++u) ea[u] = __ldcg(ETp + (i0 + 16 + u) * Kn);
            #pragma unroll
            for (int u = 0; u < 8; ++u) {
                float4 pv = pv_ptr[8 + u];
                float2 et = eb[u];
                s0 += pv.x * et.x;
                s1 += pv.z * et.x;
                float v0 = pv.y + et.y;
                float v1 = pv.w + et.y;
                if (v0 > bv0) { bv0 = v0; bi0 = hbase + i0 + 8 + u; }
                if (v1 > bv1) { bv1 = v1; bi1 = hbase + i0 + 8 + u; }
            }
            pv_ptr += 16;
        }

        if (h == 1) {
            partS[j] = make_float4(s0, s1, bv0, bv1);
            partI[j] = make_int2(bi0, bi1);
        }
        __syncthreads();

        if (h == 0) {
            float4 ps = partS[j];
            int2   pi = partI[j];
            s0 += ps.x;
            s1 += ps.y;
            // h1's indices are all >= 128 > h0's: strict > keeps first-index rule
            if (ps.z > bv0) { bv0 = ps.z; bi0 = pi.x; }
            if (ps.w > bv1) { bv1 = ps.w; bi1 = pi.y; }

            if (act0) {
                af0 = m0 + __logf(s0) + e0;
                av0 = bv0 + e0;
                bpb0[t * Kn + j] = (unsigned char)bi0;
            }
            if (act1) {
                af1 = m1 + __logf(s1) + e1;
                av1 = bv1 + e1;
                bpb1[t * Kn + j] = (unsigned char)bi1;
            }
        }
        // no extra sync needed: next writes to pva/red happen after the
        // reduction __syncthreads at the top of the next iteration.
    }

    // ---- epilogue for both batches: logZ + best_last (h=0 computes) ----
    float ev = (h == 0) ? endv[j] : 0.f;
    float afs[2] = { af0, af1 };
    float avs[2] = { av0, av1 };
    int   bs[2]  = { b0, b1 };

    #pragma unroll
    for (int sH = 0; sH < 2; ++sH) {
        float m2 = -CUDART_INF_F, z = 0.f;
        if (h == 0) {
            z = afs[sH] + ev;
            m2 = z;
            #pragma unroll
            for (int o = 16; o; o >>= 1) m2 = fmaxf(m2, __shfl_xor_sync(0xffffffffu, m2, o));
            if (lane == 0) red0[w] = m2;
        }
        __syncthreads();
        if (h == 0) {
            m2 = fmaxf(fmaxf(fmaxf(red0[0], red0[1]), fmaxf(red0[2], red0[3])),
                       fmaxf(fmaxf(red0[4], red0[5]), fmaxf(red0[6], red0[7])));
            float ex = __expf(z - m2);
            #pragma unroll
            for (int o = 16; o; o >>= 1) ex += __shfl_xor_sync(0xffffffffu, ex, o);
            if (lane == 0) red1[w] = ex;
        }
        __syncthreads();
        if (tid == 0) {
            float ssum = red1[0] + red1[1] + red1[2] + red1[3]
                       + red1[4] + red1[5] + red1[6] + red1[7];
            g_logZ[bs[sH]] = m2 + __logf(ssum);
        }

        // best_last: first argmax(viterbi alpha + end), exact linear scan
        if (h == 0) pva[j].x = avs[sH] + ev;
        __syncthreads();
        if (tid == 0) {
            float bv = pva[0].x; int bi = 0;
            for (int i = 1; i < Kn; ++i) {
                float v = pva[i].x;
                if (v > bv) { bv = v; bi = i; }
            }
            g_best[bs[sH]] = bi;
        }
        __syncthreads();
    }
}

// ---------------- K2: gold-path score per batch ------------------------------
__global__ void k2_score(
    const float* __restrict__ logit,
    const float* __restrict__ trans,
    const float* __restrict__ startv,
    const float* __restrict__ endv,
    const int*   __restrict__ target,
    const int*   __restrict__ seq_lens)
{
    int b = blockIdx.x, tid = threadIdx.x;
    int L = seq_lens[b];
    const int*   tg = target + b * Tn;
    const float* em = logit + (size_t)b * Tn * Kn;

    float part = 0.f;
    for (int t = 1 + tid; t < L; t += blockDim.x) {
        int cur = tg[t], prev = tg[t - 1];
        part += trans[prev * Kn + cur] + em[t * Kn + cur];
    }
    #pragma unroll
    for (int o = 16; o; o >>= 1) part += __shfl_xor_sync(0xffffffffu, part, o);
    __shared__ float red[4];
    if ((tid & 31) == 0) red[tid >> 5] = part;
    __syncthreads();
    if (tid == 0) {
        float s = red[0] + red[1] + red[2] + red[3];
        int t0 = tg[0];
        s += startv[t0] + em[t0];
        s += endv[tg[L - 1]];
        g_score[b] = s;
    }
}

// ---------------- K3: loss = mean(logZ - score) ------------------------------
__global__ void k3_loss(float* __restrict__ out) {
    int b = threadIdx.x;  // 128 threads
    float v = g_logZ[b] - g_score[b];
    #pragma unroll
    for (int o = 16; o; o >>= 1) v += __shfl_xor_sync(0xffffffffu, v, o);
    __shared__ float red[4];
    if ((b & 31) == 0) red[b >> 5] = v;
    __syncthreads();
    if (b == 0) out[0] = (red[0] + red[1] + red[2] + red[3]) / (float)Bn;
}

// ---------------- K4: Viterbi backtrace (128 independent chains) -------------
__global__ void k4_backtrace(const int* __restrict__ seq_lens,
                             float* __restrict__ out_pred)
{
    int b = threadIdx.x;
    if (b >= Bn) return;
    int L = seq_lens[b];
    int tag = g_best[b];
    g_pred[b * Tn + Tn - 1] = tag;
    out_pred[b * Tn + Tn - 1] = (float)tag;
    const unsigned char* bpb = g_bp + (size_t)b * Tn * Kn;
    for (int s = Tn - 2; s >= 0; --s) {
        int t = s + 1;
        if (t < L) tag = bpb[t * Kn + tag];   // masked step: identity (bp == idK)
        g_pred[b * Tn + s] = tag;
        out_pred[b * Tn + s] = (float)tag;
    }
}

// ---------------- K5: rearrange + log_softmax --------------------------------
__global__ __launch_bounds__(Kn) void k5_logits(
    const float* __restrict__ logit,
    float* __restrict__ out_lp)
{
    int row = blockIdx.x;   // b*T + t
    int j = threadIdx.x;
    int lane = j & 31, w = j >> 5;

    const float* x = logit + (size_t)row * Kn;
    float xv = x[j];

    __shared__ float sh[Kn];
    __shared__ float redv[8];
    __shared__ int   redi[8];
    sh[j] = xv;

    // argmax with first-index tie-break (exact jnp.argmax semantics)
    float bv = xv; int bi = j;
    #pragma unroll
    for (int o = 16; o; o >>= 1) {
        float ov = __shfl_xor_sync(0xffffffffu, bv, o);
        int   oi = __shfl_xor_sync(0xffffffffu, bi, o);
        if (ov > bv || (ov == bv && oi < bi)) { bv = ov; bi = oi; }
    }
    if (lane == 0) { redv[w] = bv; redi[w] = bi; }
    __syncthreads();
    float mv = redv[0]; int mi = redi[0];
    #pragma unroll
    for (int k = 1; k < 8; ++k) {
        float ov = redv[k]; int oi = redi[k];
        if (ov > mv || (ov == mv && oi < mi)) { mv = ov; mi = oi; }
    }

    int p = g_pred[row];
    float labv = sh[p];

    float y = xv;
    if (j == p)  y = mv;     // out.at[pred].set(maxv)
    if (j == mi) y = labv;   // out.at[argm].set(labv)  (applied second, as in ref)

    // log_softmax: max of rearranged array == mv (value multiset preserved)
    float ex = __expf(y - mv);
    #pragma unroll
    for (int o = 16; o; o >>= 1) ex += __shfl_xor_sync(0xffffffffu, ex, o);
    __syncthreads();
    if (lane == 0) redv[w] = ex;
    __syncthreads();
    float ssum = redv[0] + redv[1] + redv[2] + redv[3]
               + redv[4] + redv[5] + redv[6] + redv[7];
    out_lp[(size_t)row * Kn + j] = y - mv - __logf(ssum);
}

// ---------------- launch ------------------------------------------------------
extern "C" void kernel_launch(void* const* d_in, const int* in_sizes, int n_in,
                              void* d_out, int out_size)
{
    (void)in_sizes; (void)n_in; (void)out_size;
    const float* logit  = (const float*)d_in[0];   // [B,T,K] f32
    const float* trans  = (const float*)d_in[1];   // [K,K]   f32
    const float* startv = (const float*)d_in[2];   // [K]     f32
    const float* endv   = (const float*)d_in[3];   // [K]     f32
    const int*   target = (const int*)d_in[4];     // [B,T]   i32
    const int*   seqlen = (const int*)d_in[5];     // [B]     i32

    float* out      = (float*)d_out;
    float* out_pred = out + 1;              // [B,T]   (pred cast to f32)
    float* out_lp   = out + 1 + Bn * Tn;    // [B,T,K]

    k0_prep<<<(Kn * Kn + 255) / 256, 256>>>(trans);
    k1_scan2<<<HB, 512>>>(logit, startv, endv, seqlen);
    k2_score<<<Bn, 128>>>(logit, trans, startv, endv, target, seqlen);
    k3_loss<<<1, 128>>>(out);
    k4_backtrace<<<1, 128>>>(seqlen, out_pred);
    k5_logits<<<Bn * Tn, Kn>>>(logit, out_lp);
}

// round 10
// speedup vs baseline: 2.5588x; 1.5277x over previous
#include <cuda_runtime.h>
#include <math_constants.h>

#define Bn 128
#define Tn 512
#define Kn 256
#define HB 64   // half of Bn: CTAs in k1, each owning batches (b, b+HB)

// ---------------- scratch (static device globals; no allocation allowed) ----
// pad: 3-stage prefetch pipeline reads up to 16 rows past the end (zero-init).
__device__ float2 g_ET[Kn * Kn + 16 * Kn];       // (exp(trans), trans) interleaved
__device__ float  g_transT[Kn * Kn];             // trans transposed: [j][i]
__device__ float  g_av[(size_t)Bn * Tn * Kn];    // Viterbi alphas (64 MiB)
__device__ float  g_logZ[Bn];
__device__ float  g_score[Bn];
__device__ int    g_best[Bn];
__device__ int    g_pred[Bn * Tn];

// ---------------- K0: build (exp(t), t) matrix + transposed trans -------------
__global__ void k0_prep(const float* __restrict__ trans) {
    int idx = blockIdx.x * blockDim.x + threadIdx.x;
    if (idx < Kn * Kn) {
        float t = trans[idx];
        g_ET[idx] = make_float2(__expf(t), t);
        int i = idx >> 8, j = idx & 255;
        g_transT[j * Kn + i] = t;
    }
}

// ---------------- K1: fused forward(logZ) + Viterbi max scan ------------------
// 2 batches/CTA, 512 threads: thread (j, h) owns output state j (=tid&255) and
// source half h (=tid>>8). No argmax tracking: only max value (FMNMX); the
// fp32 Viterbi alphas are stored to g_av and backpointers are recomputed
// exactly during backtrace. 3-deep prefetch pipeline on the ET stream.
__global__ __launch_bounds__(512, 1) void k1_scan2(
    const float* __restrict__ logit,
    const float* __restrict__ startv,
    const float* __restrict__ endv,
    const int*   __restrict__ seq_lens)
{
    int b0 = blockIdx.x;
    int b1 = blockIdx.x + HB;
    int tid = threadIdx.x;
    int j = tid & 255;
    int h = tid >> 8;
    int lane = tid & 31, w = tid >> 5;   // h0 warps are 0..7

    __shared__ float4 pva[Kn];     // (p0_i, av0_i, p1_i, av1_i)
    __shared__ float4 partS[Kn];   // h=1 partials: (s0, s1, bv0, bv1)
    __shared__ float  red0[8], red1[8];

    int L0 = seq_lens[b0];
    int L1 = seq_lens[b1];
    int Lmax = max(L0, L1);

    const float* em0 = logit + (size_t)b0 * Tn * Kn;
    const float* em1 = logit + (size_t)b1 * Tn * Kn;
    float* avg0 = g_av + (size_t)b0 * Tn * Kn;
    float* avg1 = g_av + (size_t)b1 * Tn * Kn;

    float af0 = 0.f, av0 = 0.f, af1 = 0.f, av1 = 0.f;
    if (h == 0) {
        float sv = startv[j];
        af0 = sv + em0[j]; av0 = af0;
        af1 = sv + em1[j]; av1 = af1;
        __stcg(avg0 + j, av0);          // av at t=0 (needed by backtrace)
        __stcg(avg1 + j, av1);
    }

    int hbase = h << 7;                               // 0 or 128
    const float2* ETp = g_ET + j + (size_t)hbase * Kn;

    for (int t = 1; t < Lmax; ++t) {
        bool act0 = t < L0, act1 = t < L1;

        float e0 = 0.f, e1 = 0.f, m0 = 0.f, m1 = 0.f;
        if (h == 0) {
            e0 = __ldg(em0 + t * Kn + j);
            e1 = __ldg(em1 + t * Kn + j);
            m0 = af0; m1 = af1;
            #pragma unroll
            for (int o = 16; o; o >>= 1) {
                m0 = fmaxf(m0, __shfl_xor_sync(0xffffffffu, m0, o));
                m1 = fmaxf(m1, __shfl_xor_sync(0xffffffffu, m1, o));
            }
            if (lane == 0) { red0[w] = m0; red1[w] = m1; }
        }
        __syncthreads();
        if (h == 0) {
            m0 = fmaxf(fmaxf(fmaxf(red0[0], red0[1]), fmaxf(red0[2], red0[3])),
                       fmaxf(fmaxf(red0[4], red0[5]), fmaxf(red0[6], red0[7])));
            m1 = fmaxf(fmaxf(fmaxf(red1[0], red1[1]), fmaxf(red1[2], red1[3])),
                       fmaxf(fmaxf(red1[4], red1[5]), fmaxf(red1[6], red1[7])));
            pva[j] = make_float4(__expf(af0 - m0), av0, __expf(af1 - m1), av1);
        }
        __syncthreads();

        // ---- inner half-K: 16 stages of 8 rows, 3-stage rolling prefetch ----
        float s0 = 0.f, s1 = 0.f;
        float bv0 = -CUDART_INF_F, bv1 = -CUDART_INF_F;

        float2 buf[3][8];
        #pragma unroll
        for (int u = 0; u < 8; ++u) buf[0][u] = __ldcg(ETp + u * Kn);
        #pragma unroll
        for (int u = 0; u < 8; ++u) buf[1][u] = __ldcg(ETp + (8 + u) * Kn);

        const float4* pv_ptr = pva + hbase;

        #pragma unroll
        for (int s = 0; s < 16; ++s) {
            // prefetch stage s+2 (stages 16,17 read the zero pad rows)
            #pragma unroll
            for (int u = 0; u < 8; ++u)
                buf[(s + 2) % 3][u] = __ldcg(ETp + ((s + 2) * 8 + u) * Kn);
            // compute stage s
            #pragma unroll
            for (int u = 0; u < 8; ++u) {
                float4 pv = pv_ptr[s * 8 + u];
                float2 et = buf[s % 3][u];
                s0 += pv.x * et.x;
                s1 += pv.z * et.x;
                bv0 = fmaxf(bv0, pv.y + et.y);   // exact fp32 add + exact max
                bv1 = fmaxf(bv1, pv.w + et.y);
            }
        }

        if (h == 1) partS[j] = make_float4(s0, s1, bv0, bv1);
        __syncthreads();

        if (h == 0) {
            float4 ps = partS[j];
            s0 += ps.x;
            s1 += ps.y;
            bv0 = fmaxf(bv0, ps.z);
            bv1 = fmaxf(bv1, ps.w);

            if (act0) {
                af0 = m0 + __logf(s0) + e0;
                av0 = bv0 + e0;
                __stcg(avg0 + t * Kn + j, av0);
            }
            if (act1) {
                af1 = m1 + __logf(s1) + e1;
                av1 = bv1 + e1;
                __stcg(avg1 + t * Kn + j, av1);
            }
        }
        // next-iteration top __syncthreads orders partS reads vs rewrites
    }

    // ---- epilogue for both batches: logZ + best_last (h=0 computes) ----
    float ev = (h == 0) ? endv[j] : 0.f;
    float afs[2] = { af0, af1 };
    float avs[2] = { av0, av1 };
    int   bs[2]  = { b0, b1 };

    #pragma unroll
    for (int sH = 0; sH < 2; ++sH) {
        float m2 = -CUDART_INF_F, z = 0.f;
        if (h == 0) {
            z = afs[sH] + ev;
            m2 = z;
            #pragma unroll
            for (int o = 16; o; o >>= 1) m2 = fmaxf(m2, __shfl_xor_sync(0xffffffffu, m2, o));
            if (lane == 0) red0[w] = m2;
        }
        __syncthreads();
        if (h == 0) {
            m2 = fmaxf(fmaxf(fmaxf(red0[0], red0[1]), fmaxf(red0[2], red0[3])),
                       fmaxf(fmaxf(red0[4], red0[5]), fmaxf(red0[6], red0[7])));
            float ex = __expf(z - m2);
            #pragma unroll
            for (int o = 16; o; o >>= 1) ex += __shfl_xor_sync(0xffffffffu, ex, o);
            if (lane == 0) red1[w] = ex;
        }
        __syncthreads();
        if (tid == 0) {
            float ssum = red1[0] + red1[1] + red1[2] + red1[3]
                       + red1[4] + red1[5] + red1[6] + red1[7];
            g_logZ[bs[sH]] = m2 + __logf(ssum);
        }

        // best_last: first argmax(viterbi alpha + end), exact linear scan
        if (h == 0) pva[j].x = avs[sH] + ev;
        __syncthreads();
        if (tid == 0) {
            float bv = pva[0].x; int bi = 0;
            for (int i = 1; i < Kn; ++i) {
                float v = pva[i].x;
                if (v > bv) { bv = v; bi = i; }
            }
            g_best[bs[sH]] = bi;
        }
        __syncthreads();
    }
}

// ---------------- K2: gold-path score per batch ------------------------------
__global__ void k2_score(
    const float* __restrict__ logit,
    const float* __restrict__ trans,
    const float* __restrict__ startv,
    const float* __restrict__ endv,
    const int*   __restrict__ target,
    const int*   __restrict__ seq_lens)
{
    int b = blockIdx.x, tid = threadIdx.x;
    int L = seq_lens[b];
    const int*   tg = target + b * Tn;
    const float* em = logit + (size_t)b * Tn * Kn;

    float part = 0.f;
    for (int t = 1 + tid; t < L; t += blockDim.x) {
        int cur = tg[t], prev = tg[t - 1];
        part += trans[prev * Kn + cur] + em[t * Kn + cur];
    }
    #pragma unroll
    for (int o = 16; o; o >>= 1) part += __shfl_xor_sync(0xffffffffu, part, o);
    __shared__ float red[4];
    if ((tid & 31) == 0) red[tid >> 5] = part;
    __syncthreads();
    if (tid == 0) {
        float s = red[0] + red[1] + red[2] + red[3];
        int t0 = tg[0];
        s += startv[t0] + em[t0];
        s += endv[tg[L - 1]];
        g_score[b] = s;
    }
}

// ---------------- K3: loss = mean(logZ - score) ------------------------------
__global__ void k3_loss(float* __restrict__ out) {
    int b = threadIdx.x;  // 128 threads
    float v = g_logZ[b] - g_score[b];
    #pragma unroll
    for (int o = 16; o; o >>= 1) v += __shfl_xor_sync(0xffffffffu, v, o);
    __shared__ float red[4];
    if ((b & 31) == 0) red[b >> 5] = v;
    __syncthreads();
    if (b == 0) out[0] = (red[0] + red[1] + red[2] + red[3]) / (float)Bn;
}

// ---------------- K4: backtrace with on-the-fly backpointer recompute --------
// One warp per batch. bp[t][tag] = argmax_i(av[t-1][i] + trans[i][tag]) is
// recomputed exactly: same fp32 adds, first-index tie-break (per-lane
// ascending i with strict >, cross-lane min-index on equal values).
__global__ void k4_backtrace(const int* __restrict__ seq_lens,
                             float* __restrict__ out_pred)
{
    int b = blockIdx.x;
    int lane = threadIdx.x;
    int L = seq_lens[b];
    int tag = g_best[b];
    const float* avb = g_av + (size_t)b * Tn * Kn;

    if (lane == 0) {
        g_pred[b * Tn + Tn - 1] = tag;
        out_pred[b * Tn + Tn - 1] = (float)tag;
    }

    // prefetch av row for the first active step
    float avr[8];
    {
        const float* row = avb + (size_t)(min(L, Tn) - 2) * Kn;  // t-1 for t=L-1
        #pragma unroll
        for (int k = 0; k < 8; ++k) avr[k] = __ldcg(row + k * 32 + lane);
    }

    for (int s = Tn - 2; s >= 0; --s) {
        int t = s + 1;
        if (t < L) {
            const float* trow = g_transT + tag * Kn;
            float bv = -CUDART_INF_F; int bi = 0;
            #pragma unroll
            for (int k = 0; k < 8; ++k) {
                float v = avr[k] + __ldg(trow + k * 32 + lane);
                if (v > bv) { bv = v; bi = k * 32 + lane; }   // ascending i: first
            }
            // prefetch next av row (independent of the reduce below)
            if (t - 2 >= 0) {
                const float* row = avb + (size_t)(t - 2) * Kn;
                #pragma unroll
                for (int k = 0; k < 8; ++k) avr[k] = __ldcg(row + k * 32 + lane);
            }
            // cross-lane argmax, min-index tie-break
            #pragma unroll
            for (int o = 16; o; o >>= 1) {
                float ov = __shfl_xor_sync(0xffffffffu, bv, o);
                int   oi = __shfl_xor_sync(0xffffffffu, bi, o);
                if (ov > bv || (ov == bv && oi < bi)) { bv = ov; bi = oi; }
            }
            tag = bi;
        }
        if (lane == 0) {
            g_pred[b * Tn + s] = tag;
            out_pred[b * Tn + s] = (float)tag;
        }
    }
}

// ---------------- K5: rearrange + log_softmax --------------------------------
__global__ __launch_bounds__(Kn) void k5_logits(
    const float* __restrict__ logit,
    float* __restrict__ out_lp)
{
    int row = blockIdx.x;   // b*T + t
    int j = threadIdx.x;
    int lane = j & 31, w = j >> 5;

    const float* x = logit + (size_t)row * Kn;
    float xv = x[j];

    __shared__ float sh[Kn];
    __shared__ float redv[8];
    __shared__ int   redi[8];
    sh[j] = xv;

    // argmax with first-index tie-break (exact jnp.argmax semantics)
    float bv = xv; int bi = j;
    #pragma unroll
    for (int o = 16; o; o >>= 1) {
        float ov = __shfl_xor_sync(0xffffffffu, bv, o);
        int   oi = __shfl_xor_sync(0xffffffffu, bi, o);
        if (ov > bv || (ov == bv && oi < bi)) { bv = ov; bi = oi; }
    }
    if (lane == 0) { redv[w] = bv; redi[w] = bi; }
    __syncthreads();
    float mv = redv[0]; int mi = redi[0];
    #pragma unroll
    for (int k = 1; k < 8; ++k) {
        float ov = redv[k]; int oi = redi[k];
        if (ov > mv || (ov == mv && oi < mi)) { mv = ov; mi = oi; }
    }

    int p = g_pred[row];
    float labv = sh[p];

    float y = xv;
    if (j == p)  y = mv;     // out.at[pred].set(maxv)
    if (j == mi) y = labv;   // out.at[argm].set(labv)  (applied second, as in ref)

    // log_softmax: max of rearranged array == mv (value multiset preserved)
    float ex = __expf(y - mv);
    #pragma unroll
    for (int o = 16; o; o >>= 1) ex += __shfl_xor_sync(0xffffffffu, ex, o);
    __syncthreads();
    if (lane == 0) redv[w] = ex;
    __syncthreads();
    float ssum = redv[0] + redv[1] + redv[2] + redv[3]
               + redv[4] + redv[5] + redv[6] + redv[7];
    out_lp[(size_t)row * Kn + j] = y - mv - __logf(ssum);
}

// ---------------- launch ------------------------------------------------------
extern "C" void kernel_launch(void* const* d_in, const int* in_sizes, int n_in,
                              void* d_out, int out_size)
{
    (void)in_sizes; (void)n_in; (void)out_size;
    const float* logit  = (const float*)d_in[0];   // [B,T,K] f32
    const float* trans  = (const float*)d_in[1];   // [K,K]   f32
    const float* startv = (const float*)d_in[2];   // [K]     f32
    const float* endv   = (const float*)d_in[3];   // [K]     f32
    const int*   target = (const int*)d_in[4];     // [B,T]   i32
    const int*   seqlen = (const int*)d_in[5];     // [B]     i32

    float* out      = (float*)d_out;
    float* out_pred = out + 1;              // [B,T]   (pred cast to f32)
    float* out_lp   = out + 1 + Bn * Tn;    // [B,T,K]

    k0_prep<<<(Kn * Kn + 255) / 256, 256>>>(trans);
    k1_scan2<<<HB, 512>>>(logit, startv, endv, seqlen);
    k2_score<<<Bn, 128>>>(logit, trans, startv, endv, target, seqlen);
    k3_loss<<<1, 128>>>(out);
    k4_backtrace<<<Bn, 32>>>(seqlen, out_pred);
    k5_logits<<<Bn * Tn, Kn>>>(logit, out_lp);
}

// round 11
// speedup vs baseline: 3.2462x; 1.2686x over previous
#include <cuda_runtime.h>
#include <math_constants.h>
#include <cooperative_groups.h>

namespace cg = cooperative_groups;

#define Bn 128
#define Tn 512
#define Kn 256
#define HB 64   // clusters in k1; cluster c owns batches (c, c+HB)

// ---------------- scratch (static device globals; no allocation allowed) ----
// pad: prefetch pipeline reads up to 16 rows past the end (zero-init).
__device__ float2 g_ET[Kn * Kn + 16 * Kn];       // (exp(trans), trans) interleaved
__device__ float  g_transT[Kn * Kn];             // trans transposed: [j][i]
__device__ float  g_av[(size_t)Bn * Tn * Kn];    // Viterbi alphas (64 MiB)
__device__ float  g_logZ[Bn];
__device__ float  g_score[Bn];
__device__ int    g_best[Bn];
__device__ int    g_pred[Bn * Tn];

// ---------------- K0: build (exp(t), t) matrix + transposed trans -------------
__global__ void k0_prep(const float* __restrict__ trans) {
    int idx = blockIdx.x * blockDim.x + threadIdx.x;
    if (idx < Kn * Kn) {
        float t = trans[idx];
        g_ET[idx] = make_float2(__expf(t), t);
        int i = idx >> 8, j = idx & 255;
        g_transT[j * Kn + i] = t;
    }
}

// ---------------- K1: clustered forward(logZ) + Viterbi max scan --------------
// 2-CTA cluster per batch pair (b0=c, b1=c+HB). CTA rank r owns output columns
// j in [r*128, r*128+128) -> reads only its 128 ET columns (256 KB/step).
// Per step the 2 KB of (af, av) state is exchanged via DSMEM (double-buffered)
// with ONE cluster.sync. Thread (jl, h): jl=tid&127 output col, h=tid>>7 owns
// source rows [h*64, h*64+64). No argmax in the hot loop; av stored to g_av.
__global__ void __cluster_dims__(2, 1, 1) __launch_bounds__(512, 1) k1_scan(
    const float* __restrict__ logit,
    const float* __restrict__ startv,
    const float* __restrict__ endv,
    const int*   __restrict__ seq_lens)
{
    cg::cluster_group cl = cg::this_cluster();
    const unsigned r = cl.block_rank();           // 0 or 1

    int cid = blockIdx.x >> 1;
    int b0 = cid, b1 = cid + HB;
    int tid = threadIdx.x;
    int jl = tid & 127;
    int h = tid >> 7;                             // 0..3
    int j = (int)r * 128 + jl;                    // global output column
    int lane = tid & 31, w = tid >> 5;            // warps 0..15

    __shared__ float4 s_afav[2][Kn];   // parity-buffered (af0, av0, af1, av1), all i
    __shared__ float4 s_pva[Kn];       // (p0, av0, p1, av1), all i
    __shared__ float4 s_part[3][128];  // h=1..3 partials (s0, s1, bv0, bv1)
    __shared__ float  red0[8], red1[8];

    float4* peer_afav = (float4*)cl.map_shared_rank(&s_afav[0][0], r ^ 1);

    int L0 = seq_lens[b0];
    int L1 = seq_lens[b1];
    int Lmax = max(L0, L1);

    const float* em0 = logit + (size_t)b0 * Tn * Kn;
    const float* em1 = logit + (size_t)b1 * Tn * Kn;
    float* avg0 = g_av + (size_t)b0 * Tn * Kn;
    float* avg1 = g_av + (size_t)b1 * Tn * Kn;

    float af0 = 0.f, av0 = 0.f, af1 = 0.f, av1 = 0.f;
    if (h == 0) {
        float sv = startv[j];
        af0 = sv + __ldg(em0 + j); av0 = af0;
        af1 = sv + __ldg(em1 + j); av1 = af1;
        __stcg(avg0 + j, av0);                 // av at t=0 (backtrace needs it)
        __stcg(avg1 + j, av1);
    }

    const float2* ETp = g_ET + j + (size_t)(h * 64) * Kn;

    for (int t = 1; t < Lmax; ++t) {
        int p = t & 1;
        bool act0 = t < L0, act1 = t < L1;

        float e0 = 0.f, e1 = 0.f;
        if (h == 0) {
            e0 = __ldg(em0 + t * Kn + j);
            e1 = __ldg(em1 + t * Kn + j);
            float4 st4 = make_float4(af0, av0, af1, av1);
            s_afav[p][j] = st4;                 // own half, local
            peer_afav[p * Kn + j] = st4;        // own half -> peer's smem
        }
        cl.sync();                               // exchange + full ordering

        // ---- global max over all 256 forward alphas (both batches) ----
        if (tid < 256) {
            float4 a = s_afav[p][tid];
            float x0 = a.x, x1 = a.z;
            #pragma unroll
            for (int o = 16; o; o >>= 1) {
                x0 = fmaxf(x0, __shfl_xor_sync(0xffffffffu, x0, o));
                x1 = fmaxf(x1, __shfl_xor_sync(0xffffffffu, x1, o));
            }
            if (lane == 0) { red0[w] = x0; red1[w] = x1; }
        }
        __syncthreads();
        float m0 = fmaxf(fmaxf(fmaxf(red0[0], red0[1]), fmaxf(red0[2], red0[3])),
                         fmaxf(fmaxf(red0[4], red0[5]), fmaxf(red0[6], red0[7])));
        float m1 = fmaxf(fmaxf(fmaxf(red1[0], red1[1]), fmaxf(red1[2], red1[3])),
                         fmaxf(fmaxf(red1[4], red1[5]), fmaxf(red1[6], red1[7])));
        if (tid < 256) {
            float4 a = s_afav[p][tid];
            s_pva[tid] = make_float4(__expf(a.x - m0), a.y, __expf(a.z - m1), a.w);
        }
        __syncthreads();

        // ---- inner quarter-K: 8 stages of 8 rows, 3-stage rolling prefetch ----
        float s0 = 0.f, s1 = 0.f;
        float bv0 = -CUDART_INF_F, bv1 = -CUDART_INF_F;

        float2 buf[3][8];
        #pragma unroll
        for (int u = 0; u < 8; ++u) buf[0][u] = __ldcg(ETp + u * Kn);
        #pragma unroll
        for (int u = 0; u < 8; ++u) buf[1][u] = __ldcg(ETp + (8 + u) * Kn);

        const float4* pv_ptr = s_pva + h * 64;

        #pragma unroll
        for (int s = 0; s < 8; ++s) {
            // prefetch stage s+2 (stages 8,9 read past-quarter rows; pad-safe)
            #pragma unroll
            for (int u = 0; u < 8; ++u)
                buf[(s + 2) % 3][u] = __ldcg(ETp + ((s + 2) * 8 + u) * Kn);
            // compute stage s
            #pragma unroll
            for (int u = 0; u < 8; ++u) {
                float4 pv = pv_ptr[s * 8 + u];
                float2 et = buf[s % 3][u];
                s0 += pv.x * et.x;
                s1 += pv.z * et.x;
                bv0 = fmaxf(bv0, pv.y + et.y);   // exact fp32 add + exact max
                bv1 = fmaxf(bv1, pv.w + et.y);
            }
        }

        if (h) s_part[h - 1][jl] = make_float4(s0, s1, bv0, bv1);
        __syncthreads();

        if (h == 0) {
            #pragma unroll
            for (int q = 0; q < 3; ++q) {
                float4 ps = s_part[q][jl];
                s0 += ps.x;
                s1 += ps.y;
                bv0 = fmaxf(bv0, ps.z);
                bv1 = fmaxf(bv1, ps.w);
            }
            if (act0) {
                af0 = m0 + __logf(s0) + e0;
                av0 = bv0 + e0;
                __stcg(avg0 + t * Kn + j, av0);
            }
            if (act1) {
                af1 = m1 + __logf(s1) + e1;
                av1 = bv1 + e1;
                __stcg(avg1 + t * Kn + j, av1);
            }
        }
        // next step's cl.sync orders these updates vs peer reads
    }

    // ---- epilogue: exchange (af+end, av+end); rank 0 reduces ----
    int pe = Lmax & 1;
    if (h == 0) {
        float ev = endv[j];
        float4 st4 = make_float4(af0 + ev, av0 + ev, af1 + ev, av1 + ev);
        s_afav[pe][j] = st4;
        peer_afav[pe * Kn + j] = st4;
    }
    cl.sync();

    if (r == 0) {
        // logZ = logsumexp over 256 z-values, both batches
        float z0 = 0.f, z1 = 0.f;
        if (tid < 256) {
            float4 a = s_afav[pe][tid];
            z0 = a.x; z1 = a.z;
            float x0 = z0, x1 = z1;
            #pragma unroll
            for (int o = 16; o; o >>= 1) {
                x0 = fmaxf(x0, __shfl_xor_sync(0xffffffffu, x0, o));
                x1 = fmaxf(x1, __shfl_xor_sync(0xffffffffu, x1, o));
            }
            if (lane == 0) { red0[w] = x0; red1[w] = x1; }
        }
        __syncthreads();
        float m0 = fmaxf(fmaxf(fmaxf(red0[0], red0[1]), fmaxf(red0[2], red0[3])),
                         fmaxf(fmaxf(red0[4], red0[5]), fmaxf(red0[6], red0[7])));
        float m1 = fmaxf(fmaxf(fmaxf(red1[0], red1[1]), fmaxf(red1[2], red1[3])),
                         fmaxf(fmaxf(red1[4], red1[5]), fmaxf(red1[6], red1[7])));
        __syncthreads();
        if (tid < 256) {
            float ex0 = __expf(z0 - m0);
            float ex1 = __expf(z1 - m1);
            #pragma unroll
            for (int o = 16; o; o >>= 1) {
                ex0 += __shfl_xor_sync(0xffffffffu, ex0, o);
                ex1 += __shfl_xor_sync(0xffffffffu, ex1, o);
            }
            if (lane == 0) { red0[w] = ex0; red1[w] = ex1; }
        }
        __syncthreads();
        if (tid == 0) {
            float ss0 = red0[0] + red0[1] + red0[2] + red0[3]
                      + red0[4] + red0[5] + red0[6] + red0[7];
            float ss1 = red1[0] + red1[1] + red1[2] + red1[3]
                      + red1[4] + red1[5] + red1[6] + red1[7];
            g_logZ[b0] = m0 + __logf(ss0);
            g_logZ[b1] = m1 + __logf(ss1);
            // best_last: first argmax, exact ascending linear scan
            float bv = s_afav[pe][0].y; int bi = 0;
            float bw = s_afav[pe][0].w; int bj = 0;
            for (int i = 1; i < Kn; ++i) {
                float v = s_afav[pe][i].y;
                float u = s_afav[pe][i].w;
                if (v > bv) { bv = v; bi = i; }
                if (u > bw) { bw = u; bj = i; }
            }
            g_best[b0] = bi;
            g_best[b1] = bj;
        }
    }
}

// ---------------- K2: gold-path score per batch ------------------------------
__global__ void k2_score(
    const float* __restrict__ logit,
    const float* __restrict__ trans,
    const float* __restrict__ startv,
    const float* __restrict__ endv,
    const int*   __restrict__ target,
    const int*   __restrict__ seq_lens)
{
    int b = blockIdx.x, tid = threadIdx.x;
    int L = seq_lens[b];
    const int*   tg = target + b * Tn;
    const float* em = logit + (size_t)b * Tn * Kn;

    float part = 0.f;
    for (int t = 1 + tid; t < L; t += blockDim.x) {
        int cur = tg[t], prev = tg[t - 1];
        part += trans[prev * Kn + cur] + em[t * Kn + cur];
    }
    #pragma unroll
    for (int o = 16; o; o >>= 1) part += __shfl_xor_sync(0xffffffffu, part, o);
    __shared__ float red[4];
    if ((tid & 31) == 0) red[tid >> 5] = part;
    __syncthreads();
    if (tid == 0) {
        float s = red[0] + red[1] + red[2] + red[3];
        int t0 = tg[0];
        s += startv[t0] + em[t0];
        s += endv[tg[L - 1]];
        g_score[b] = s;
    }
}

// ---------------- K3: loss = mean(logZ - score) ------------------------------
__global__ void k3_loss(float* __restrict__ out) {
    int b = threadIdx.x;  // 128 threads
    float v = g_logZ[b] - g_score[b];
    #pragma unroll
    for (int o = 16; o; o >>= 1) v += __shfl_xor_sync(0xffffffffu, v, o);
    __shared__ float red[4];
    if ((b & 31) == 0) red[b >> 5] = v;
    __syncthreads();
    if (b == 0) out[0] = (red[0] + red[1] + red[2] + red[3]) / (float)Bn;
}

// ---------------- K4: backtrace with on-the-fly backpointer recompute --------
// One warp per batch. bp[t][tag] = argmax_i(av[t-1][i] + trans[i][tag]) is
// recomputed exactly: same fp32 adds, first-index tie-break (per-lane
// ascending i with strict >, cross-lane min-index on equal values).
__global__ void k4_backtrace(const int* __restrict__ seq_lens,
                             float* __restrict__ out_pred)
{
    int b = blockIdx.x;
    int lane = threadIdx.x;
    int L = seq_lens[b];
    int tag = g_best[b];
    const float* avb = g_av + (size_t)b * Tn * Kn;

    if (lane == 0) {
        g_pred[b * Tn + Tn - 1] = tag;
        out_pred[b * Tn + Tn - 1] = (float)tag;
    }

    // prefetch av row for the first active step
    float avr[8];
    {
        const float* row = avb + (size_t)(min(L, Tn) - 2) * Kn;  // t-1 for t=L-1
        #pragma unroll
        for (int k = 0; k < 8; ++k) avr[k] = __ldcg(row + k * 32 + lane);
    }

    for (int s = Tn - 2; s >= 0; --s) {
        int t = s + 1;
        if (t < L) {
            const float* trow = g_transT + tag * Kn;
            float bv = -CUDART_INF_F; int bi = 0;
            #pragma unroll
            for (int k = 0; k < 8; ++k) {
                float v = avr[k] + __ldg(trow + k * 32 + lane);
                if (v > bv) { bv = v; bi = k * 32 + lane; }   // ascending i: first
            }
            // prefetch next av row (independent of the reduce below)
            if (t - 2 >= 0) {
                const float* row = avb + (size_t)(t - 2) * Kn;
                #pragma unroll
                for (int k = 0; k < 8; ++k) avr[k] = __ldcg(row + k * 32 + lane);
            }
            // cross-lane argmax, min-index tie-break
            #pragma unroll
            for (int o = 16; o; o >>= 1) {
                float ov = __shfl_xor_sync(0xffffffffu, bv, o);
                int   oi = __shfl_xor_sync(0xffffffffu, bi, o);
                if (ov > bv || (ov == bv && oi < bi)) { bv = ov; bi = oi; }
            }
            tag = bi;
        }
        if (lane == 0) {
            g_pred[b * Tn + s] = tag;
            out_pred[b * Tn + s] = (float)tag;
        }
    }
}

// ---------------- K5: rearrange + log_softmax --------------------------------
__global__ __launch_bounds__(Kn) void k5_logits(
    const float* __restrict__ logit,
    float* __restrict__ out_lp)
{
    int row = blockIdx.x;   // b*T + t
    int j = threadIdx.x;
    int lane = j & 31, w = j >> 5;

    const float* x = logit + (size_t)row * Kn;
    float xv = x[j];

    __shared__ float sh[Kn];
    __shared__ float redv[8];
    __shared__ int   redi[8];
    sh[j] = xv;

    // argmax with first-index tie-break (exact jnp.argmax semantics)
    float bv = xv; int bi = j;
    #pragma unroll
    for (int o = 16; o; o >>= 1) {
        float ov = __shfl_xor_sync(0xffffffffu, bv, o);
        int   oi = __shfl_xor_sync(0xffffffffu, bi, o);
        if (ov > bv || (ov == bv && oi < bi)) { bv = ov; bi = oi; }
    }
    if (lane == 0) { redv[w] = bv; redi[w] = bi; }
    __syncthreads();
    float mv = redv[0]; int mi = redi[0];
    #pragma unroll
    for (int k = 1; k < 8; ++k) {
        float ov = redv[k]; int oi = redi[k];
        if (ov > mv || (ov == mv && oi < mi)) { mv = ov; mi = oi; }
    }

    int p = g_pred[row];
    float labv = sh[p];

    float y = xv;
    if (j == p)  y = mv;     // out.at[pred].set(maxv)
    if (j == mi) y = labv;   // out.at[argm].set(labv)  (applied second, as in ref)

    // log_softmax: max of rearranged array == mv (value multiset preserved)
    float ex = __expf(y - mv);
    #pragma unroll
    for (int o = 16; o; o >>= 1) ex += __shfl_xor_sync(0xffffffffu, ex, o);
    __syncthreads();
    if (lane == 0) redv[w] = ex;
    __syncthreads();
    float ssum = redv[0] + redv[1] + redv[2] + redv[3]
               + redv[4] + redv[5] + redv[6] + redv[7];
    out_lp[(size_t)row * Kn + j] = y - mv - __logf(ssum);
}

// ---------------- launch ------------------------------------------------------
extern "C" void kernel_launch(void* const* d_in, const int* in_sizes, int n_in,
                              void* d_out, int out_size)
{
    (void)in_sizes; (void)n_in; (void)out_size;
    const float* logit  = (const float*)d_in[0];   // [B,T,K] f32
    const float* trans  = (const float*)d_in[1];   // [K,K]   f32
    const float* startv = (const float*)d_in[2];   // [K]     f32
    const float* endv   = (const float*)d_in[3];   // [K]     f32
    const int*   target = (const int*)d_in[4];     // [B,T]   i32
    const int*   seqlen = (const int*)d_in[5];     // [B]     i32

    float* out      = (float*)d_out;
    float* out_pred = out + 1;              // [B,T]   (pred cast to f32)
    float* out_lp   = out + 1 + Bn * Tn;    // [B,T,K]

    k0_prep<<<(Kn * Kn + 255) / 256, 256>>>(trans);
    k1_scan<<<2 * HB, 512>>>(logit, startv, endv, seqlen);   // 64 clusters x 2 CTAs
    k2_score<<<Bn, 128>>>(logit, trans, startv, endv, target, seqlen);
    k3_loss<<<1, 128>>>(out);
    k4_backtrace<<<Bn, 32>>>(seqlen, out_pred);
    k5_logits<<<Bn * Tn, Kn>>>(logit, out_lp);
}